// round 16
// baseline (speedup 1.0000x reference)
#include <cuda_runtime.h>
#include <cuda_fp16.h>
#include <math.h>
#include <stdint.h>

#define BATCH 2
#define SEQ   2048
#define CDIM  2048
#define NH    16
#define NKV   4
#define HD    128
#define KVC   (NKV*HD)   // 512
#define GRP   (NH/NKV)   // 4
#define NQKV  (CDIM+2*KVC) // 3072

// ---------------- scratch (__device__ globals) ------------------------------
__device__ __half g_xh[BATCH*SEQ*CDIM];
__device__ __half g_wqkv[NQKV*CDIM];          // [3072, 2048] fp16, row = out col
__device__ __half g_wo[CDIM*CDIM];            // [2048, 2048]
__device__ __half g_qh[BATCH*SEQ*CDIM];
__device__ __half g_kh[BATCH*SEQ*KVC];
__device__ __half g_vh[BATCH*SEQ*KVC];
__device__ __half g_oh[BATCH*SEQ*CDIM];
__device__ float2 g_cs[SEQ*(HD/2)];           // rope cos/sin table

// ---------------- helpers ---------------------------------------------------
__device__ __forceinline__ uint32_t smem_u32(const void* p) {
    uint32_t a;
    asm("{ .reg .u64 t; cvta.to.shared.u64 t, %1; cvt.u32.u64 %0, t; }"
        : "=r"(a) : "l"(p));
    return a;
}
__device__ __forceinline__ void cp16(uint32_t dst, const void* src) {
    asm volatile("cp.async.cg.shared.global [%0], [%1], 16;"
                 :: "r"(dst), "l"(src));
}
__device__ __forceinline__ void cp_commit() {
    asm volatile("cp.async.commit_group;");
}
template <int N>
__device__ __forceinline__ void cp_wait() {
    asm volatile("cp.async.wait_group %0;" :: "n"(N));
}
__device__ __forceinline__ void ldsm4(uint32_t* r, uint32_t addr) {
    asm volatile("ldmatrix.sync.aligned.m8n8.x4.shared.b16 {%0,%1,%2,%3}, [%4];"
                 : "=r"(r[0]), "=r"(r[1]), "=r"(r[2]), "=r"(r[3]) : "r"(addr));
}
__device__ __forceinline__ void ldsm4t(uint32_t* r, uint32_t addr) {
    asm volatile("ldmatrix.sync.aligned.m8n8.x4.trans.shared.b16 {%0,%1,%2,%3}, [%4];"
                 : "=r"(r[0]), "=r"(r[1]), "=r"(r[2]), "=r"(r[3]) : "r"(addr));
}
__device__ __forceinline__ void mma_f16(float* c, const uint32_t* a,
                                        const uint32_t* b) {
    asm volatile(
        "mma.sync.aligned.m16n8k16.row.col.f32.f16.f16.f32 "
        "{%0,%1,%2,%3}, {%4,%5,%6,%7}, {%8,%9}, {%0,%1,%2,%3};"
        : "+f"(c[0]), "+f"(c[1]), "+f"(c[2]), "+f"(c[3])
        : "r"(a[0]), "r"(a[1]), "r"(a[2]), "r"(a[3]), "r"(b[0]), "r"(b[1]));
}
__device__ __forceinline__ uint32_t packh(float lo, float hi) {
    uint32_t r;
    asm("cvt.rn.f16x2.f32 %0, %1, %2;" : "=r"(r) : "f"(hi), "f"(lo));
    return r;
}

// ---------------------------------------------------------------------------
// Prep kernels
// ---------------------------------------------------------------------------
__global__ void build_cs(float2* cs) {
    int idx = blockIdx.x * blockDim.x + threadIdx.x;
    if (idx >= SEQ * (HD / 2)) return;
    int p = idx >> 6;
    int i = idx & 63;
    float inv = expf(-(2.0f * (float)i / (float)HD) * 9.210340371976184f);
    float ang = (float)p * inv;
    float s, c;
    sincosf(ang, &s, &c);
    cs[idx] = make_float2(c, s);
}

__global__ void conv_x(const float* __restrict__ src,
                       __half* __restrict__ dst, int n) {
    int i = blockIdx.x * blockDim.x + threadIdx.x;
    if (i >= n) return;
    dst[i] = __float2half_rn(src[i]);
}

// All four weight transposes in one launch. z: 0=Wq, 1=Wk, 2=Wv, 3=Wo.
__global__ __launch_bounds__(256) void transpose_all(
    const float* __restrict__ Wq, const float* __restrict__ Wk,
    const float* __restrict__ Wv, const float* __restrict__ Wo,
    __half* __restrict__ wqkv, __half* __restrict__ wo) {
    __shared__ float t[32][33];
    const int z = blockIdx.z;
    const float* W;
    __half* dst;
    int Nn, rowoff;
    if (z == 0)      { W = Wq; dst = wqkv; Nn = CDIM; rowoff = 0; }
    else if (z == 1) { W = Wk; dst = wqkv; Nn = KVC;  rowoff = CDIM; }
    else if (z == 2) { W = Wv; dst = wqkv; Nn = KVC;  rowoff = CDIM + KVC; }
    else             { W = Wo; dst = wo;   Nn = CDIM; rowoff = 0; }
    int bx = blockIdx.x * 32;   // n
    if (bx >= Nn) return;
    int by = blockIdx.y * 32;   // k
    int tx = threadIdx.x & 31;
    int ty = threadIdx.x >> 5;
    #pragma unroll
    for (int i = 0; i < 32; i += 8)
        t[ty + i][tx] = W[(size_t)(by + ty + i) * Nn + bx + tx];
    __syncthreads();
    #pragma unroll
    for (int i = 0; i < 32; i += 8) {
        int r = ty + i;
        dst[(size_t)(rowoff + bx + r) * CDIM + by + tx] = __float2half_rn(t[tx][r]);
    }
}

// ---------------------------------------------------------------------------
// 1-term fp16 GEMM core:  acc = A[M,K] @ (B[N,K])^T   (fp32 accum)
// CTA 128x128, BK=32, 8 warps (4m x 2n), warp tile 32x64.
// 3-stage cp.async ring, ONE sync per chunk (CUTLASS order, proven R13):
//   wait(group kc) -> sync -> compute stage kc -> issue stage kc+2.
// __launch_bounds__(256,3) caps regs at 85 -> 3 CTAs/SM (24 warps, 6/SMSP).
// ---------------------------------------------------------------------------
#define GBM 128
#define GBN 128
#define BKC 32
#define ASTRB 80                   // bytes per smem row (32 fp16 = 64B + 16 pad)
#define TILEB (128*ASTRB)          // 10240
#define STG   (2*TILEB)            // 20480 (A, B)
#define GSM   (3*STG)              // 61440

#define GEMM1_LOAD_STAGE(ST_, KK_, A_, B_)                                      \
    {                                                                           \
        _Pragma("unroll")                                                       \
        for (int t = 0; t < 4; t++) {                                           \
            int c = tid + t * 256;                                              \
            int tile = c >> 9;                                                  \
            int cc = c & 511;                                                   \
            int row = cc >> 2, c16 = cc & 3;                                    \
            uint32_t dst = (ST_) + tile * TILEB + row * ASTRB + c16 * 16;       \
            const __half* src = (tile == 0 ? (A_) + (size_t)(m0 + row) * CDIM   \
                                           : (B_) + (size_t)(n0 + row) * CDIM)  \
                              + (KK_) + c16 * 8;                                \
            cp16(dst, src);                                                     \
        }                                                                       \
        cp_commit();                                                            \
    }

#define GEMM1_MAINLOOP(A_, B_)                                                  \
    const uint32_t aoff = (uint32_t)(mbase + (lane & 15)) * ASTRB + (lane >> 4) * 16; \
    const uint32_t boff = (uint32_t)(nbase + ((lane >> 4) << 3) + (lane & 7)) * ASTRB \
                        + ((lane >> 3) & 1) * 16;                               \
    float acc[2][8][4];                                                         \
    _Pragma("unroll")                                                           \
    for (int mi = 0; mi < 2; mi++)                                              \
        _Pragma("unroll")                                                       \
        for (int j = 0; j < 8; j++)                                             \
            _Pragma("unroll")                                                   \
            for (int e = 0; e < 4; e++) acc[mi][j][e] = 0.f;                    \
    const int nchunks = CDIM / BKC;                                             \
    GEMM1_LOAD_STAGE(sb, 0, A_, B_)                                             \
    GEMM1_LOAD_STAGE(sb + STG, BKC, A_, B_)                                     \
    for (int kc = 0; kc < nchunks; kc++) {                                      \
        if (kc + 1 < nchunks) { cp_wait<1>(); } else { cp_wait<0>(); }          \
        __syncthreads();   /* stage kc%3 fully landed for ALL threads */        \
        const uint32_t st = sb + (kc % 3) * STG;                                \
        _Pragma("unroll")                                                       \
        for (int ks = 0; ks < 2; ks++) {                                        \
            uint32_t ah[2][4];                                                  \
            _Pragma("unroll")                                                   \
            for (int mi = 0; mi < 2; mi++)                                      \
                ldsm4(ah[mi], st + aoff + mi * (16 * ASTRB) + ks * 32);         \
            _Pragma("unroll")                                                   \
            for (int np = 0; np < 4; np++) {                                    \
                uint32_t bfr[4];                                                \
                ldsm4(bfr, st + TILEB + boff + np * (16 * ASTRB) + ks * 32);    \
                _Pragma("unroll")                                               \
                for (int mi = 0; mi < 2; mi++) {                                \
                    mma_f16(acc[mi][np * 2],     ah[mi], bfr);                  \
                    mma_f16(acc[mi][np * 2 + 1], ah[mi], bfr + 2);              \
                }                                                               \
            }                                                                   \
        }                                                                       \
        if (kc + 2 < nchunks) {                                                 \
            const uint32_t stw = sb + ((kc + 2) % 3) * STG;                     \
            GEMM1_LOAD_STAGE(stw, (kc + 2) * BKC, A_, B_)                       \
        }                                                                       \
    }

// QKV projection with fused bias + RoPE + fp16 epilogue.
// q is scaled by (1/sqrt(D)) * log2(e) so flash can use exp2f directly.
__global__ __launch_bounds__(256, 3) void gemm_qkv(
    const __half* __restrict__ Ax, const __half* __restrict__ Bw,
    const float* __restrict__ bq, const float* __restrict__ bk,
    const float* __restrict__ bv, const int* __restrict__ pid,
    const float2* __restrict__ cs,
    __half* __restrict__ qh, __half* __restrict__ kh, __half* __restrict__ vh) {
    extern __shared__ char smem[];
    const uint32_t sb = smem_u32(smem);
    const int tid = threadIdx.x;
    const int wid = tid >> 5;
    const int lane = tid & 31;
    const int m0 = blockIdx.y * GBM;
    const int n0 = blockIdx.x * GBN;
    const int mbase = (wid & 3) * 32;
    const int nbase = (wid >> 2) * 64;

    GEMM1_MAINLOOP(Ax, Bw)

    const float qscale = 0.12751741f;   // (1/sqrt(128)) * log2(e)
    const int r0 = lane >> 2;
    const int c0q = (lane & 3) * 2;
    const int region = (n0 < CDIM) ? 0 : (n0 < CDIM + KVC ? 1 : 2);
    #pragma unroll
    for (int mi = 0; mi < 2; mi++) {
        const int rowa = m0 + mbase + mi * 16 + r0;
        const int rowb = rowa + 8;
        #pragma unroll
        for (int j = 0; j < 8; j++) {
            const int col = n0 + nbase + j * 8 + c0q;
            float a0 = acc[mi][j][0], a1 = acc[mi][j][1];
            float b0 = acc[mi][j][2], b1 = acc[mi][j][3];
            if (region == 0) {
                a0 += bq[col]; a1 += bq[col + 1];
                b0 += bq[col]; b1 += bq[col + 1];
                int i = (col & (HD - 1)) >> 1;
                float2 c_a = cs[pid[rowa] * 64 + i];
                float2 c_b = cs[pid[rowb] * 64 + i];
                float y0 = (a0 * c_a.x - a1 * c_a.y) * qscale;
                float y1 = (a1 * c_a.x + a0 * c_a.y) * qscale;
                float z0 = (b0 * c_b.x - b1 * c_b.y) * qscale;
                float z1 = (b1 * c_b.x + b0 * c_b.y) * qscale;
                *(uint32_t*)&qh[(size_t)rowa * CDIM + col] = packh(y0, y1);
                *(uint32_t*)&qh[(size_t)rowb * CDIM + col] = packh(z0, z1);
            } else if (region == 1) {
                int kc = col - CDIM;
                a0 += bk[kc]; a1 += bk[kc + 1];
                b0 += bk[kc]; b1 += bk[kc + 1];
                int i = (kc & (HD - 1)) >> 1;
                float2 c_a = cs[pid[rowa] * 64 + i];
                float2 c_b = cs[pid[rowb] * 64 + i];
                *(uint32_t*)&kh[(size_t)rowa * KVC + kc] =
                    packh(a0 * c_a.x - a1 * c_a.y, a1 * c_a.x + a0 * c_a.y);
                *(uint32_t*)&kh[(size_t)rowb * KVC + kc] =
                    packh(b0 * c_b.x - b1 * c_b.y, b1 * c_b.x + b0 * c_b.y);
            } else {
                int vc = col - CDIM - KVC;
                a0 += bv[vc]; a1 += bv[vc + 1];
                b0 += bv[vc]; b1 += bv[vc + 1];
                *(uint32_t*)&vh[(size_t)rowa * KVC + vc] = packh(a0, a1);
                *(uint32_t*)&vh[(size_t)rowb * KVC + vc] = packh(b0, b1);
            }
        }
    }
}

// Output projection: fp32 epilogue to d_out
__global__ __launch_bounds__(256, 3) void gemm_out(
    const __half* __restrict__ Ah, const __half* __restrict__ Bw,
    float* __restrict__ C) {
    extern __shared__ char smem[];
    const uint32_t sb = smem_u32(smem);
    const int tid = threadIdx.x;
    const int wid = tid >> 5;
    const int lane = tid & 31;
    const int m0 = blockIdx.y * GBM;
    const int n0 = blockIdx.x * GBN;
    const int mbase = (wid & 3) * 32;
    const int nbase = (wid >> 2) * 64;

    GEMM1_MAINLOOP(Ah, Bw)

    const int r0 = lane >> 2;
    const int c0q = (lane & 3) * 2;
    #pragma unroll
    for (int mi = 0; mi < 2; mi++) {
        const int rowa = m0 + mbase + mi * 16 + r0;
        #pragma unroll
        for (int j = 0; j < 8; j++) {
            const int col = n0 + nbase + j * 8 + c0q;
            *(float2*)&C[(size_t)rowa * CDIM + col] =
                make_float2(acc[mi][j][0], acc[mi][j][1]);
            *(float2*)&C[(size_t)(rowa + 8) * CDIM + col] =
                make_float2(acc[mi][j][2], acc[mi][j][3]);
        }
    }
}

// ---------------------------------------------------------------------------
// fp16 causal GQA flash attention (exp2-domain softmax; q pre-scaled by log2e).
// CTA: 64 q rows, 4 warps (16 rows each). KV tile 64. Structure = R13 (proven).
// ---------------------------------------------------------------------------
#define FSTR 272
#define FTILE (64*FSTR)            // 17408
#define SM_Q  0
#define SM_K  (1*FTILE)
#define SM_V  (2*FTILE)
#define FSMEM (3*FTILE)            // 52224

__global__ __launch_bounds__(128) void flash_attn_f16(
    const __half* __restrict__ qh, const __half* __restrict__ kh,
    const __half* __restrict__ vh, __half* __restrict__ oh) {
    extern __shared__ char smem[];
    const uint32_t sb = smem_u32(smem);
    const int tid = threadIdx.x;
    const int warp = tid >> 5;
    const int lane = tid & 31;
    const int qt = gridDim.x - 1 - blockIdx.x;   // longest CTAs first
    const int bh_ = blockIdx.y;
    const int b = bh_ / NH, h = bh_ % NH;
    const int kvh = h / GRP;
    const int q0 = qt * 64;

    // load Q tile, its own commit group
    {
        const __half* qp = qh + (size_t)(b * SEQ + q0) * CDIM + h * HD;
        #pragma unroll
        for (int t = 0; t < 8; t++) {
            int c = tid + t * 128;
            int row = c >> 4, ch = c & 15;
            cp16(sb + SM_Q + row * FSTR + ch * 16, qp + (size_t)row * CDIM + ch * 8);
        }
        cp_commit();
    }

    const uint32_t aoff = (uint32_t)(warp * 16 + (lane & 15)) * FSTR + (lane >> 4) * 16;
    const uint32_t boff = (uint32_t)(((lane >> 4) << 3) + (lane & 7)) * FSTR
                        + ((lane >> 3) & 1) * 16;
    const uint32_t voff = (uint32_t)((((lane >> 3) & 1) << 3) + (lane & 7)) * FSTR
                        + (lane >> 4) * 16;

    float oacc[16][4];
    #pragma unroll
    for (int t = 0; t < 16; t++)
        #pragma unroll
        for (int e = 0; e < 4; e++) oacc[t][e] = 0.f;
    float m0v = -1e30f, m1v = -1e30f, l0 = 0.f, l1 = 0.f;

    const __half* kb = kh + (size_t)(b * SEQ) * KVC + kvh * HD;
    const __half* vb = vh + (size_t)(b * SEQ) * KVC + kvh * HD;

    for (int kt = 0; kt <= qt; kt++) {
        const int k0 = kt * 64;
        // K group
        #pragma unroll
        for (int t = 0; t < 8; t++) {
            int c = tid + t * 128;
            int row = c >> 4, ch = c & 15;
            cp16(sb + SM_K + row * FSTR + ch * 16,
                 kb + (size_t)(k0 + row) * KVC + ch * 8);
        }
        cp_commit();
        // V group
        #pragma unroll
        for (int t = 0; t < 8; t++) {
            int c = tid + t * 128;
            int row = c >> 4, ch = c & 15;
            cp16(sb + SM_V + row * FSTR + ch * 16,
                 vb + (size_t)(k0 + row) * KVC + ch * 8);
        }
        cp_commit();
        cp_wait<1>();        // Q (first iter) + K ready; V may still be in flight
        __syncthreads();

        // S = Q K^T   (already in log2 domain via q pre-scale)
        float s[8][4];
        #pragma unroll
        for (int nt = 0; nt < 8; nt++)
            #pragma unroll
            for (int e = 0; e < 4; e++) s[nt][e] = 0.f;

        #pragma unroll
        for (int ks = 0; ks < 8; ks++) {
            uint32_t ah[4];
            ldsm4(ah, sb + SM_Q + aoff + ks * 32);
            #pragma unroll
            for (int np = 0; np < 4; np++) {
                uint32_t bf[4];
                ldsm4(bf, sb + SM_K + boff + np * (16 * FSTR) + ks * 32);
                mma_f16(s[np * 2],     ah, bf);
                mma_f16(s[np * 2 + 1], ah, bf + 2);
            }
        }

        // causal mask on diagonal tile
        const int rg0 = q0 + warp * 16 + (lane >> 2);
        if (kt == qt) {
            #pragma unroll
            for (int nt = 0; nt < 8; nt++) {
                int colb = k0 + nt * 8 + 2 * (lane & 3);
                #pragma unroll
                for (int e = 0; e < 4; e++) {
                    int col = colb + (e & 1);
                    int row = rg0 + ((e >> 1) ? 8 : 0);
                    if (col > row) s[nt][e] = -1e30f;
                }
            }
        }

        // online softmax (base-2)
        float mx0 = -1e30f, mx1 = -1e30f;
        #pragma unroll
        for (int nt = 0; nt < 8; nt++) {
            mx0 = fmaxf(mx0, fmaxf(s[nt][0], s[nt][1]));
            mx1 = fmaxf(mx1, fmaxf(s[nt][2], s[nt][3]));
        }
        mx0 = fmaxf(mx0, __shfl_xor_sync(0xffffffffu, mx0, 1));
        mx0 = fmaxf(mx0, __shfl_xor_sync(0xffffffffu, mx0, 2));
        mx1 = fmaxf(mx1, __shfl_xor_sync(0xffffffffu, mx1, 1));
        mx1 = fmaxf(mx1, __shfl_xor_sync(0xffffffffu, mx1, 2));

        float mn0 = fmaxf(m0v, mx0);
        float mn1 = fmaxf(m1v, mx1);
        float al0 = exp2f(m0v - mn0);
        float al1 = exp2f(m1v - mn1);
        m0v = mn0; m1v = mn1;

        float sum0 = 0.f, sum1 = 0.f;
        #pragma unroll
        for (int nt = 0; nt < 8; nt++) {
            float p0 = exp2f(s[nt][0] - mn0);
            float p1 = exp2f(s[nt][1] - mn0);
            float p2 = exp2f(s[nt][2] - mn1);
            float p3 = exp2f(s[nt][3] - mn1);
            s[nt][0] = p0; s[nt][1] = p1; s[nt][2] = p2; s[nt][3] = p3;
            sum0 += p0 + p1;
            sum1 += p2 + p3;
        }
        sum0 += __shfl_xor_sync(0xffffffffu, sum0, 1);
        sum0 += __shfl_xor_sync(0xffffffffu, sum0, 2);
        sum1 += __shfl_xor_sync(0xffffffffu, sum1, 1);
        sum1 += __shfl_xor_sync(0xffffffffu, sum1, 2);
        l0 = l0 * al0 + sum0;
        l1 = l1 * al1 + sum1;

        // rescale accumulators only when the running max actually moved
        if (__any_sync(0xffffffffu, (al0 != 1.f) || (al1 != 1.f))) {
            #pragma unroll
            for (int t = 0; t < 16; t++) {
                oacc[t][0] *= al0; oacc[t][1] *= al0;
                oacc[t][2] *= al1; oacc[t][3] *= al1;
            }
        }

        cp_wait<0>();        // V ready now
        __syncthreads();

        // O += P V   (single-term fp16 P)
        #pragma unroll
        for (int kc = 0; kc < 4; kc++) {
            uint32_t pah[4];
            #pragma unroll
            for (int half = 0; half < 2; half++) {
                const int nt = 2 * kc + half;
                pah[half * 2 + 0] = packh(s[nt][0], s[nt][1]);
                pah[half * 2 + 1] = packh(s[nt][2], s[nt][3]);
            }
            #pragma unroll
            for (int dc = 0; dc < 8; dc++) {
                uint32_t vf[4];
                ldsm4t(vf, sb + SM_V + voff + kc * (16 * FSTR) + dc * 32);
                mma_f16(oacc[dc * 2],     pah, vf);
                mma_f16(oacc[dc * 2 + 1], pah, vf + 2);
            }
        }
        __syncthreads();     // protect K/V smem before next tile's loads
    }

    // normalize, round once to fp16, write
    const float il0 = 1.f / l0;
    const float il1 = 1.f / l1;
    const int rowg = b * SEQ + q0 + warp * 16 + (lane >> 2);
    const int colg = h * HD + (lane & 3) * 2;
    #pragma unroll
    for (int nt = 0; nt < 16; nt++) {
        size_t o0 = (size_t)rowg * CDIM + colg + nt * 8;
        size_t o1 = (size_t)(rowg + 8) * CDIM + colg + nt * 8;
        *(uint32_t*)&oh[o0] = packh(oacc[nt][0] * il0, oacc[nt][1] * il0);
        *(uint32_t*)&oh[o1] = packh(oacc[nt][2] * il1, oacc[nt][3] * il1);
    }
}

// ---------------------------------------------------------------------------
extern "C" void kernel_launch(void* const* d_in, const int* in_sizes, int n_in,
                              void* d_out, int out_size) {
    const float* x   = (const float*)d_in[0];
    const int*   pid = (const int*)d_in[1];
    const float* Wq  = (const float*)d_in[2];
    const float* bq  = (const float*)d_in[3];
    const float* Wk  = (const float*)d_in[4];
    const float* bk  = (const float*)d_in[5];
    const float* Wv  = (const float*)d_in[6];
    const float* bv  = (const float*)d_in[7];
    const float* Wo  = (const float*)d_in[8];
    float* out = (float*)d_out;

    __half *xh, *wqkv, *wo, *qh, *kh, *vh, *oh;
    float2* cs;
    cudaGetSymbolAddress((void**)&xh, g_xh);
    cudaGetSymbolAddress((void**)&wqkv, g_wqkv);
    cudaGetSymbolAddress((void**)&wo, g_wo);
    cudaGetSymbolAddress((void**)&qh, g_qh);
    cudaGetSymbolAddress((void**)&kh, g_kh);
    cudaGetSymbolAddress((void**)&vh, g_vh);
    cudaGetSymbolAddress((void**)&oh, g_oh);
    cudaGetSymbolAddress((void**)&cs, g_cs);

    const int M = BATCH * SEQ;   // 4096

    // prep
    build_cs<<<(SEQ * 64 + 255) / 256, 256>>>(cs);
    int nx = M * CDIM;
    conv_x<<<(nx + 255) / 256, 256>>>(x, xh, nx);
    transpose_all<<<dim3(CDIM / 32, CDIM / 32, 4), 256>>>(Wq, Wk, Wv, Wo, wqkv, wo);

    // fused QKV projection + bias + RoPE (q pre-scaled into log2 domain)
    cudaFuncSetAttribute(gemm_qkv, cudaFuncAttributeMaxDynamicSharedMemorySize, GSM);
    gemm_qkv<<<dim3(NQKV / GBN, M / GBM), 256, GSM>>>(
        xh, wqkv, bq, bk, bv, pid, cs, qh, kh, vh);

    // flash attention (all single-term fp16, exp2 softmax)
    cudaFuncSetAttribute(flash_attn_f16, cudaFuncAttributeMaxDynamicSharedMemorySize, FSMEM);
    flash_attn_f16<<<dim3(SEQ / 64, BATCH * NH), 128, FSMEM>>>(qh, kh, vh, oh);

    // output projection straight to d_out
    cudaFuncSetAttribute(gemm_out, cudaFuncAttributeMaxDynamicSharedMemorySize, GSM);
    gemm_out<<<dim3(CDIM / GBN, M / GBM), 256, GSM>>>(oh, wo, out);
}

// round 17
// speedup vs baseline: 1.5461x; 1.5461x over previous
#include <cuda_runtime.h>
#include <cuda_fp16.h>
#include <math.h>
#include <stdint.h>

#define BATCH 2
#define SEQ   2048
#define CDIM  2048
#define NH    16
#define NKV   4
#define HD    128
#define KVC   (NKV*HD)   // 512
#define GRP   (NH/NKV)   // 4
#define NQKV  (CDIM+2*KVC) // 3072

// ---------------- scratch (__device__ globals) ------------------------------
__device__ __half g_xh[BATCH*SEQ*CDIM];
__device__ __half g_wqkv[NQKV*CDIM];          // [3072, 2048] fp16, row = out col
__device__ __half g_wo[CDIM*CDIM];            // [2048, 2048]
__device__ __half g_qh[BATCH*SEQ*CDIM];
__device__ __half g_kh[BATCH*SEQ*KVC];
__device__ __half g_vh[BATCH*SEQ*KVC];
__device__ __half g_oh[BATCH*SEQ*CDIM];
__device__ float2 g_cs[SEQ*(HD/2)];           // rope cos/sin table

// ---------------- helpers ---------------------------------------------------
__device__ __forceinline__ uint32_t smem_u32(const void* p) {
    uint32_t a;
    asm("{ .reg .u64 t; cvta.to.shared.u64 t, %1; cvt.u32.u64 %0, t; }"
        : "=r"(a) : "l"(p));
    return a;
}
__device__ __forceinline__ void cp16(uint32_t dst, const void* src) {
    asm volatile("cp.async.cg.shared.global [%0], [%1], 16;"
                 :: "r"(dst), "l"(src));
}
__device__ __forceinline__ void cp_commit() {
    asm volatile("cp.async.commit_group;");
}
template <int N>
__device__ __forceinline__ void cp_wait() {
    asm volatile("cp.async.wait_group %0;" :: "n"(N));
}
__device__ __forceinline__ void ldsm4(uint32_t* r, uint32_t addr) {
    asm volatile("ldmatrix.sync.aligned.m8n8.x4.shared.b16 {%0,%1,%2,%3}, [%4];"
                 : "=r"(r[0]), "=r"(r[1]), "=r"(r[2]), "=r"(r[3]) : "r"(addr));
}
__device__ __forceinline__ void ldsm4t(uint32_t* r, uint32_t addr) {
    asm volatile("ldmatrix.sync.aligned.m8n8.x4.trans.shared.b16 {%0,%1,%2,%3}, [%4];"
                 : "=r"(r[0]), "=r"(r[1]), "=r"(r[2]), "=r"(r[3]) : "r"(addr));
}
__device__ __forceinline__ void mma_f16(float* c, const uint32_t* a,
                                        const uint32_t* b) {
    asm volatile(
        "mma.sync.aligned.m16n8k16.row.col.f32.f16.f16.f32 "
        "{%0,%1,%2,%3}, {%4,%5,%6,%7}, {%8,%9}, {%0,%1,%2,%3};"
        : "+f"(c[0]), "+f"(c[1]), "+f"(c[2]), "+f"(c[3])
        : "r"(a[0]), "r"(a[1]), "r"(a[2]), "r"(a[3]), "r"(b[0]), "r"(b[1]));
}
__device__ __forceinline__ uint32_t packh(float lo, float hi) {
    uint32_t r;
    asm("cvt.rn.f16x2.f32 %0, %1, %2;" : "=r"(r) : "f"(hi), "f"(lo));
    return r;
}

// ---------------------------------------------------------------------------
// Prep kernels
// ---------------------------------------------------------------------------
// conv_x and build_cs fused into one launch.
__global__ void prep_x_cs(const float* __restrict__ src,
                          __half* __restrict__ dst, int n, float2* cs) {
    int i = blockIdx.x * blockDim.x + threadIdx.x;
    if (i < n) {
        dst[i] = __float2half_rn(src[i]);
    } else {
        int idx = i - n;
        if (idx < SEQ * (HD / 2)) {
            int p = idx >> 6;
            int j = idx & 63;
            float inv = expf(-(2.0f * (float)j / (float)HD) * 9.210340371976184f);
            float ang = (float)p * inv;
            float s, c;
            sincosf(ang, &s, &c);
            cs[idx] = make_float2(c, s);
        }
    }
}

// All four weight transposes in one launch. z: 0=Wq, 1=Wk, 2=Wv, 3=Wo.
__global__ __launch_bounds__(256) void transpose_all(
    const float* __restrict__ Wq, const float* __restrict__ Wk,
    const float* __restrict__ Wv, const float* __restrict__ Wo,
    __half* __restrict__ wqkv, __half* __restrict__ wo) {
    __shared__ float t[32][33];
    const int z = blockIdx.z;
    const float* W;
    __half* dst;
    int Nn, rowoff;
    if (z == 0)      { W = Wq; dst = wqkv; Nn = CDIM; rowoff = 0; }
    else if (z == 1) { W = Wk; dst = wqkv; Nn = KVC;  rowoff = CDIM; }
    else if (z == 2) { W = Wv; dst = wqkv; Nn = KVC;  rowoff = CDIM + KVC; }
    else             { W = Wo; dst = wo;   Nn = CDIM; rowoff = 0; }
    int bx = blockIdx.x * 32;   // n
    if (bx >= Nn) return;
    int by = blockIdx.y * 32;   // k
    int tx = threadIdx.x & 31;
    int ty = threadIdx.x >> 5;
    #pragma unroll
    for (int i = 0; i < 32; i += 8)
        t[ty + i][tx] = W[(size_t)(by + ty + i) * Nn + bx + tx];
    __syncthreads();
    #pragma unroll
    for (int i = 0; i < 32; i += 8) {
        int r = ty + i;
        dst[(size_t)(rowoff + bx + r) * CDIM + by + tx] = __float2half_rn(t[tx][r]);
    }
}

// ---------------------------------------------------------------------------
// 1-term fp16 GEMM core (R13 config — proven 466.8us global best):
// CTA 128x128, BK=64, 8 warps (4m x 2n), warp tile 32x64.
// 3-stage cp.async ring, ONE sync per chunk, CUTLASS order:
//   wait(group kc) -> sync -> compute stage kc -> issue stage kc+2.
// ---------------------------------------------------------------------------
#define GBM 128
#define GBN 128
#define BKC 64
#define ASTRB 144                  // bytes per smem row (64 fp16 = 128B + 16 pad)
#define TILEB (128*ASTRB)          // 18432
#define STG   (2*TILEB)            // 36864 (A, B)
#define GSM   (3*STG)              // 110592

#define GEMM1_LOAD_STAGE(ST_, KK_, A_, B_)                                      \
    {                                                                           \
        _Pragma("unroll")                                                       \
        for (int t = 0; t < 8; t++) {                                           \
            int c = tid + t * 256;                                              \
            int tile = c >> 10;                                                 \
            int cc = c & 1023;                                                  \
            int row = cc >> 3, c16 = cc & 7;                                    \
            uint32_t dst = (ST_) + tile * TILEB + row * ASTRB + c16 * 16;       \
            const __half* src = (tile == 0 ? (A_) + (size_t)(m0 + row) * CDIM   \
                                           : (B_) + (size_t)(n0 + row) * CDIM)  \
                              + (KK_) + c16 * 8;                                \
            cp16(dst, src);                                                     \
        }                                                                       \
        cp_commit();                                                            \
    }

#define GEMM1_MAINLOOP(A_, B_)                                                  \
    const uint32_t aoff = (uint32_t)(mbase + (lane & 15)) * ASTRB + (lane >> 4) * 16; \
    const uint32_t boff = (uint32_t)(nbase + ((lane >> 4) << 3) + (lane & 7)) * ASTRB \
                        + ((lane >> 3) & 1) * 16;                               \
    float acc[2][8][4];                                                         \
    _Pragma("unroll")                                                           \
    for (int mi = 0; mi < 2; mi++)                                              \
        _Pragma("unroll")                                                       \
        for (int j = 0; j < 8; j++)                                             \
            _Pragma("unroll")                                                   \
            for (int e = 0; e < 4; e++) acc[mi][j][e] = 0.f;                    \
    const int nchunks = CDIM / BKC;                                             \
    GEMM1_LOAD_STAGE(sb, 0, A_, B_)                                             \
    GEMM1_LOAD_STAGE(sb + STG, BKC, A_, B_)                                     \
    for (int kc = 0; kc < nchunks; kc++) {                                      \
        if (kc + 1 < nchunks) { cp_wait<1>(); } else { cp_wait<0>(); }          \
        __syncthreads();   /* stage kc%3 fully landed for ALL threads */        \
        const uint32_t st = sb + (kc % 3) * STG;                                \
        _Pragma("unroll")                                                       \
        for (int ks = 0; ks < 4; ks++) {                                        \
            uint32_t ah[2][4];                                                  \
            _Pragma("unroll")                                                   \
            for (int mi = 0; mi < 2; mi++)                                      \
                ldsm4(ah[mi], st + aoff + mi * (16 * ASTRB) + ks * 32);         \
            _Pragma("unroll")                                                   \
            for (int np = 0; np < 4; np++) {                                    \
                uint32_t bfr[4];                                                \
                ldsm4(bfr, st + TILEB + boff + np * (16 * ASTRB) + ks * 32);    \
                _Pragma("unroll")                                               \
                for (int mi = 0; mi < 2; mi++) {                                \
                    mma_f16(acc[mi][np * 2],     ah[mi], bfr);                  \
                    mma_f16(acc[mi][np * 2 + 1], ah[mi], bfr + 2);              \
                }                                                               \
            }                                                                   \
        }                                                                       \
        if (kc + 2 < nchunks) {                                                 \
            const uint32_t stw = sb + ((kc + 2) % 3) * STG;                     \
            GEMM1_LOAD_STAGE(stw, (kc + 2) * BKC, A_, B_)                       \
        }                                                                       \
    }

// QKV projection with fused bias + RoPE + fp16 epilogue.
// q is scaled by (1/sqrt(D)) * log2(e) so flash can use exp2f directly.
__global__ __launch_bounds__(256) void gemm_qkv(
    const __half* __restrict__ Ax, const __half* __restrict__ Bw,
    const float* __restrict__ bq, const float* __restrict__ bk,
    const float* __restrict__ bv, const int* __restrict__ pid,
    const float2* __restrict__ cs,
    __half* __restrict__ qh, __half* __restrict__ kh, __half* __restrict__ vh) {
    extern __shared__ char smem[];
    const uint32_t sb = smem_u32(smem);
    const int tid = threadIdx.x;
    const int wid = tid >> 5;
    const int lane = tid & 31;
    const int m0 = blockIdx.y * GBM;
    const int n0 = blockIdx.x * GBN;
    const int mbase = (wid & 3) * 32;
    const int nbase = (wid >> 2) * 64;

    GEMM1_MAINLOOP(Ax, Bw)

    const float qscale = 0.12751741f;   // (1/sqrt(128)) * log2(e)
    const int r0 = lane >> 2;
    const int c0q = (lane & 3) * 2;
    const int region = (n0 < CDIM) ? 0 : (n0 < CDIM + KVC ? 1 : 2);
    #pragma unroll
    for (int mi = 0; mi < 2; mi++) {
        const int rowa = m0 + mbase + mi * 16 + r0;
        const int rowb = rowa + 8;
        #pragma unroll
        for (int j = 0; j < 8; j++) {
            const int col = n0 + nbase + j * 8 + c0q;
            float a0 = acc[mi][j][0], a1 = acc[mi][j][1];
            float b0 = acc[mi][j][2], b1 = acc[mi][j][3];
            if (region == 0) {
                a0 += bq[col]; a1 += bq[col + 1];
                b0 += bq[col]; b1 += bq[col + 1];
                int i = (col & (HD - 1)) >> 1;
                float2 c_a = cs[pid[rowa] * 64 + i];
                float2 c_b = cs[pid[rowb] * 64 + i];
                float y0 = (a0 * c_a.x - a1 * c_a.y) * qscale;
                float y1 = (a1 * c_a.x + a0 * c_a.y) * qscale;
                float z0 = (b0 * c_b.x - b1 * c_b.y) * qscale;
                float z1 = (b1 * c_b.x + b0 * c_b.y) * qscale;
                *(uint32_t*)&qh[(size_t)rowa * CDIM + col] = packh(y0, y1);
                *(uint32_t*)&qh[(size_t)rowb * CDIM + col] = packh(z0, z1);
            } else if (region == 1) {
                int kc = col - CDIM;
                a0 += bk[kc]; a1 += bk[kc + 1];
                b0 += bk[kc]; b1 += bk[kc + 1];
                int i = (kc & (HD - 1)) >> 1;
                float2 c_a = cs[pid[rowa] * 64 + i];
                float2 c_b = cs[pid[rowb] * 64 + i];
                *(uint32_t*)&kh[(size_t)rowa * KVC + kc] =
                    packh(a0 * c_a.x - a1 * c_a.y, a1 * c_a.x + a0 * c_a.y);
                *(uint32_t*)&kh[(size_t)rowb * KVC + kc] =
                    packh(b0 * c_b.x - b1 * c_b.y, b1 * c_b.x + b0 * c_b.y);
            } else {
                int vc = col - CDIM - KVC;
                a0 += bv[vc]; a1 += bv[vc + 1];
                b0 += bv[vc]; b1 += bv[vc + 1];
                *(uint32_t*)&vh[(size_t)rowa * KVC + vc] = packh(a0, a1);
                *(uint32_t*)&vh[(size_t)rowb * KVC + vc] = packh(b0, b1);
            }
        }
    }
}

// Output projection: fp32 epilogue to d_out
__global__ __launch_bounds__(256) void gemm_out(
    const __half* __restrict__ Ah, const __half* __restrict__ Bw,
    float* __restrict__ C) {
    extern __shared__ char smem[];
    const uint32_t sb = smem_u32(smem);
    const int tid = threadIdx.x;
    const int wid = tid >> 5;
    const int lane = tid & 31;
    const int m0 = blockIdx.y * GBM;
    const int n0 = blockIdx.x * GBN;
    const int mbase = (wid & 3) * 32;
    const int nbase = (wid >> 2) * 64;

    GEMM1_MAINLOOP(Ah, Bw)

    const int r0 = lane >> 2;
    const int c0q = (lane & 3) * 2;
    #pragma unroll
    for (int mi = 0; mi < 2; mi++) {
        const int rowa = m0 + mbase + mi * 16 + r0;
        #pragma unroll
        for (int j = 0; j < 8; j++) {
            const int col = n0 + nbase + j * 8 + c0q;
            *(float2*)&C[(size_t)rowa * CDIM + col] =
                make_float2(acc[mi][j][0], acc[mi][j][1]);
            *(float2*)&C[(size_t)(rowa + 8) * CDIM + col] =
                make_float2(acc[mi][j][2], acc[mi][j][3]);
        }
    }
}

// ---------------------------------------------------------------------------
// fp16 causal GQA flash attention (exp2 softmax; q pre-scaled by log2e).
// CTA: 64 q rows, 4 warps. KV tile 64.
// Software pipelined loads: next K overlaps PV; next V overlaps next S.
// ---------------------------------------------------------------------------
#define FSTR 272
#define FTILE (64*FSTR)            // 17408
#define SM_Q  0
#define SM_K  (1*FTILE)
#define SM_V  (2*FTILE)
#define FSMEM (3*FTILE)            // 52224

__global__ __launch_bounds__(128) void flash_attn_f16(
    const __half* __restrict__ qh, const __half* __restrict__ kh,
    const __half* __restrict__ vh, __half* __restrict__ oh) {
    extern __shared__ char smem[];
    const uint32_t sb = smem_u32(smem);
    const int tid = threadIdx.x;
    const int warp = tid >> 5;
    const int lane = tid & 31;
    const int qt = gridDim.x - 1 - blockIdx.x;   // longest CTAs first
    const int bh_ = blockIdx.y;
    const int b = bh_ / NH, h = bh_ % NH;
    const int kvh = h / GRP;
    const int q0 = qt * 64;

    const __half* kb = kh + (size_t)(b * SEQ) * KVC + kvh * HD;
    const __half* vb = vh + (size_t)(b * SEQ) * KVC + kvh * HD;

    // Prologue: Q group, then K0 group, then V0 group (3 separate groups)
    {
        const __half* qp = qh + (size_t)(b * SEQ + q0) * CDIM + h * HD;
        #pragma unroll
        for (int t = 0; t < 8; t++) {
            int c = tid + t * 128;
            int row = c >> 4, ch = c & 15;
            cp16(sb + SM_Q + row * FSTR + ch * 16, qp + (size_t)row * CDIM + ch * 8);
        }
        cp_commit();
        #pragma unroll
        for (int t = 0; t < 8; t++) {
            int c = tid + t * 128;
            int row = c >> 4, ch = c & 15;
            cp16(sb + SM_K + row * FSTR + ch * 16, kb + (size_t)row * KVC + ch * 8);
        }
        cp_commit();
        #pragma unroll
        for (int t = 0; t < 8; t++) {
            int c = tid + t * 128;
            int row = c >> 4, ch = c & 15;
            cp16(sb + SM_V + row * FSTR + ch * 16, vb + (size_t)row * KVC + ch * 8);
        }
        cp_commit();
    }

    const uint32_t aoff = (uint32_t)(warp * 16 + (lane & 15)) * FSTR + (lane >> 4) * 16;
    const uint32_t boff = (uint32_t)(((lane >> 4) << 3) + (lane & 7)) * FSTR
                        + ((lane >> 3) & 1) * 16;
    const uint32_t voff = (uint32_t)((((lane >> 3) & 1) << 3) + (lane & 7)) * FSTR
                        + (lane >> 4) * 16;

    float oacc[16][4];
    #pragma unroll
    for (int t = 0; t < 16; t++)
        #pragma unroll
        for (int e = 0; e < 4; e++) oacc[t][e] = 0.f;
    float m0v = -1e30f, m1v = -1e30f, l0 = 0.f, l1 = 0.f;

    for (int kt = 0; kt <= qt; kt++) {
        const int k0 = kt * 64;
        // Pending groups at this point: {... , K_kt, V_kt} (Q also on kt==0).
        cp_wait<1>();        // K_kt (and Q) landed; V_kt may be in flight
        __syncthreads();

        // S = Q K^T   (log2 domain)
        float s[8][4];
        #pragma unroll
        for (int nt = 0; nt < 8; nt++)
            #pragma unroll
            for (int e = 0; e < 4; e++) s[nt][e] = 0.f;

        #pragma unroll
        for (int ks = 0; ks < 8; ks++) {
            uint32_t ah[4];
            ldsm4(ah, sb + SM_Q + aoff + ks * 32);
            #pragma unroll
            for (int np = 0; np < 4; np++) {
                uint32_t bf[4];
                ldsm4(bf, sb + SM_K + boff + np * (16 * FSTR) + ks * 32);
                mma_f16(s[np * 2],     ah, bf);
                mma_f16(s[np * 2 + 1], ah, bf + 2);
            }
        }

        // causal mask on diagonal tile
        const int rg0 = q0 + warp * 16 + (lane >> 2);
        if (kt == qt) {
            #pragma unroll
            for (int nt = 0; nt < 8; nt++) {
                int colb = k0 + nt * 8 + 2 * (lane & 3);
                #pragma unroll
                for (int e = 0; e < 4; e++) {
                    int col = colb + (e & 1);
                    int row = rg0 + ((e >> 1) ? 8 : 0);
                    if (col > row) s[nt][e] = -1e30f;
                }
            }
        }

        // online softmax (base-2)
        float mx0 = -1e30f, mx1 = -1e30f;
        #pragma unroll
        for (int nt = 0; nt < 8; nt++) {
            mx0 = fmaxf(mx0, fmaxf(s[nt][0], s[nt][1]));
            mx1 = fmaxf(mx1, fmaxf(s[nt][2], s[nt][3]));
        }
        mx0 = fmaxf(mx0, __shfl_xor_sync(0xffffffffu, mx0, 1));
        mx0 = fmaxf(mx0, __shfl_xor_sync(0xffffffffu, mx0, 2));
        mx1 = fmaxf(mx1, __shfl_xor_sync(0xffffffffu, mx1, 1));
        mx1 = fmaxf(mx1, __shfl_xor_sync(0xffffffffu, mx1, 2));

        float mn0 = fmaxf(m0v, mx0);
        float mn1 = fmaxf(m1v, mx1);
        float al0 = exp2f(m0v - mn0);
        float al1 = exp2f(m1v - mn1);
        m0v = mn0; m1v = mn1;

        float sum0 = 0.f, sum1 = 0.f;
        #pragma unroll
        for (int nt = 0; nt < 8; nt++) {
            float p0 = exp2f(s[nt][0] - mn0);
            float p1 = exp2f(s[nt][1] - mn0);
            float p2 = exp2f(s[nt][2] - mn1);
            float p3 = exp2f(s[nt][3] - mn1);
            s[nt][0] = p0; s[nt][1] = p1; s[nt][2] = p2; s[nt][3] = p3;
            sum0 += p0 + p1;
            sum1 += p2 + p3;
        }
        sum0 += __shfl_xor_sync(0xffffffffu, sum0, 1);
        sum0 += __shfl_xor_sync(0xffffffffu, sum0, 2);
        sum1 += __shfl_xor_sync(0xffffffffu, sum1, 1);
        sum1 += __shfl_xor_sync(0xffffffffu, sum1, 2);
        l0 = l0 * al0 + sum0;
        l1 = l1 * al1 + sum1;

        if (__any_sync(0xffffffffu, (al0 != 1.f) || (al1 != 1.f))) {
            #pragma unroll
            for (int t = 0; t < 16; t++) {
                oacc[t][0] *= al0; oacc[t][1] *= al0;
                oacc[t][2] *= al1; oacc[t][3] *= al1;
            }
        }

        cp_wait<0>();        // V_kt landed
        __syncthreads();     // all warps past their K reads (S complete)

        // issue NEXT K load now -> overlaps PV compute
        if (kt + 1 <= qt) {
            const int kn = (kt + 1) * 64;
            #pragma unroll
            for (int t = 0; t < 8; t++) {
                int c = tid + t * 128;
                int row = c >> 4, ch = c & 15;
                cp16(sb + SM_K + row * FSTR + ch * 16,
                     kb + (size_t)(kn + row) * KVC + ch * 8);
            }
            cp_commit();
        }

        // O += P V   (single-term fp16 P)
        #pragma unroll
        for (int kc = 0; kc < 4; kc++) {
            uint32_t pah[4];
            #pragma unroll
            for (int half = 0; half < 2; half++) {
                const int nt = 2 * kc + half;
                pah[half * 2 + 0] = packh(s[nt][0], s[nt][1]);
                pah[half * 2 + 1] = packh(s[nt][2], s[nt][3]);
            }
            #pragma unroll
            for (int dc = 0; dc < 8; dc++) {
                uint32_t vf[4];
                ldsm4t(vf, sb + SM_V + voff + kc * (16 * FSTR) + dc * 32);
                mma_f16(oacc[dc * 2],     pah, vf);
                mma_f16(oacc[dc * 2 + 1], pah, vf + 2);
            }
        }
        __syncthreads();     // all warps done reading V_kt

        // issue NEXT V load -> overlaps next iteration's S compute
        if (kt + 1 <= qt) {
            const int kn = (kt + 1) * 64;
            #pragma unroll
            for (int t = 0; t < 8; t++) {
                int c = tid + t * 128;
                int row = c >> 4, ch = c & 15;
                cp16(sb + SM_V + row * FSTR + ch * 16,
                     vb + (size_t)(kn + row) * KVC + ch * 8);
            }
            cp_commit();
        }
    }

    // normalize, round once to fp16, write
    const float il0 = 1.f / l0;
    const float il1 = 1.f / l1;
    const int rowg = b * SEQ + q0 + warp * 16 + (lane >> 2);
    const int colg = h * HD + (lane & 3) * 2;
    #pragma unroll
    for (int nt = 0; nt < 16; nt++) {
        size_t o0 = (size_t)rowg * CDIM + colg + nt * 8;
        size_t o1 = (size_t)(rowg + 8) * CDIM + colg + nt * 8;
        *(uint32_t*)&oh[o0] = packh(oacc[nt][0] * il0, oacc[nt][1] * il0);
        *(uint32_t*)&oh[o1] = packh(oacc[nt][2] * il1, oacc[nt][3] * il1);
    }
}

// ---------------------------------------------------------------------------
extern "C" void kernel_launch(void* const* d_in, const int* in_sizes, int n_in,
                              void* d_out, int out_size) {
    const float* x   = (const float*)d_in[0];
    const int*   pid = (const int*)d_in[1];
    const float* Wq  = (const float*)d_in[2];
    const float* bq  = (const float*)d_in[3];
    const float* Wk  = (const float*)d_in[4];
    const float* bk  = (const float*)d_in[5];
    const float* Wv  = (const float*)d_in[6];
    const float* bv  = (const float*)d_in[7];
    const float* Wo  = (const float*)d_in[8];
    float* out = (float*)d_out;

    __half *xh, *wqkv, *wo, *qh, *kh, *vh, *oh;
    float2* cs;
    cudaGetSymbolAddress((void**)&xh, g_xh);
    cudaGetSymbolAddress((void**)&wqkv, g_wqkv);
    cudaGetSymbolAddress((void**)&wo, g_wo);
    cudaGetSymbolAddress((void**)&qh, g_qh);
    cudaGetSymbolAddress((void**)&kh, g_kh);
    cudaGetSymbolAddress((void**)&vh, g_vh);
    cudaGetSymbolAddress((void**)&oh, g_oh);
    cudaGetSymbolAddress((void**)&cs, g_cs);

    const int M = BATCH * SEQ;   // 4096

    // prep (conv_x + rope table fused; transposes in one launch)
    int nx = M * CDIM;
    int ntot = nx + SEQ * (HD / 2);
    prep_x_cs<<<(ntot + 255) / 256, 256>>>(x, xh, nx, cs);
    transpose_all<<<dim3(CDIM / 32, CDIM / 32, 4), 256>>>(Wq, Wk, Wv, Wo, wqkv, wo);

    // fused QKV projection + bias + RoPE (q pre-scaled into log2 domain)
    cudaFuncSetAttribute(gemm_qkv, cudaFuncAttributeMaxDynamicSharedMemorySize, GSM);
    gemm_qkv<<<dim3(NQKV / GBN, M / GBM), 256, GSM>>>(
        xh, wqkv, bq, bk, bv, pid, cs, qh, kh, vh);

    // flash attention (software-pipelined K/V loads)
    cudaFuncSetAttribute(flash_attn_f16, cudaFuncAttributeMaxDynamicSharedMemorySize, FSMEM);
    flash_attn_f16<<<dim3(SEQ / 64, BATCH * NH), 128, FSMEM>>>(qh, kh, vh, oh);

    // output projection straight to d_out
    cudaFuncSetAttribute(gemm_out, cudaFuncAttributeMaxDynamicSharedMemorySize, GSM);
    gemm_out<<<dim3(CDIM / GBN, M / GBM), 256, GSM>>>(oh, wo, out);
}